// round 4
// baseline (speedup 1.0000x reference)
#include <cuda_runtime.h>
#include <cuda_fp16.h>
#include <math.h>
#include <stdint.h>

// ---------------------------------------------------------------------------
// Quantizer: x [4,16,1024] f32, codebook [65536,16] f32.
// out[0:65536] = nearest codebook entry per token, [B,D,T]; out[65536] = loss.
//
// Pass 1 (tensor): fp16 mma.sync computes approx scores s = x.c (fp32 accum),
// + exact fp32 bias -0.5||c||^2 in epilogue; keep per-(token, 64-code tile)
// max only. Pass 2: exact fp32 rescore of tiles within MARGIN of the max ->
// exact argmin (identical selection math to the R1/R2 passing kernels).
// ---------------------------------------------------------------------------

#define TOKENS   4096
#define NCODES   65536
#define DIM      16
#define BW       12                 // words per B row: 8 half2 data + 4 pad
#define STC      64                 // codes per supertile
#define NST      (NCODES / STC)     // 1024
#define NGROUPS  74
#define MCTAS    4
#define MARGIN   0.5f
#define NINF     __int_as_float(0xff800000)

__device__ uint32_t g_B[(size_t)NCODES * BW];   // 3 MB packed half2
__device__ float    g_bias[NCODES];
__device__ float    g_tb[(size_t)NST * TOKENS]; // 16 MB tile maxima
__device__ float    g_err[TOKENS];

__device__ __forceinline__ void cpasync16(const void* dst_smem, const void* src) {
    unsigned s = (unsigned)__cvta_generic_to_shared(dst_smem);
    asm volatile("cp.async.cg.shared.global [%0], [%1], 16;" :: "r"(s), "l"(src));
}
#define CP_COMMIT() asm volatile("cp.async.commit_group;")
#define CP_WAIT(n)  asm volatile("cp.async.wait_group %0;" :: "n"(n))

// ---------------------------------------------------------------------------
// Phase 0: pack codebook rows to half2 words (+pad) and exact fp32 bias.
// ---------------------------------------------------------------------------
__global__ __launch_bounds__(256) void prep_kernel(const float* __restrict__ cb) {
    int i = blockIdx.x * 256 + threadIdx.x;            // code id
    const float* c = cb + (size_t)i * DIM;
    float h = 0.0f;
    uint32_t w[8];
#pragma unroll
    for (int j = 0; j < 8; j++) {
        float lo = c[2 * j], hi = c[2 * j + 1];
        h = fmaf(lo, lo, h);
        h = fmaf(hi, hi, h);
        __half2 p = __halves2half2(__float2half_rn(lo), __float2half_rn(hi));
        w[j] = *(uint32_t*)&p;
    }
    uint32_t* r = g_B + (size_t)i * BW;
#pragma unroll
    for (int j = 0; j < 8; j++) r[j] = w[j];
    r[8] = r[9] = r[10] = r[11] = 0;
    g_bias[i] = -0.5f * h;
}

// ---------------------------------------------------------------------------
// Phase 1: fp16 mma.sync scan. grid (4, 74), 256 threads, 2 CTAs/SM.
// Warp = 128 tokens (8 m16 tiles); B streamed in 64-code supertiles.
// ---------------------------------------------------------------------------
__global__ __launch_bounds__(256, 2) void scan_kernel(const float* __restrict__ x) {
    __shared__ uint32_t sB[2][STC * BW];      // 2 x 3 KB
    __shared__ float    sBias[2][STC];        // 2 x 256 B

    const int tid  = threadIdx.x;
    const int wid  = tid >> 5, lane = tid & 31;
    const int gid  = lane >> 2, tg = lane & 3;
    const int bx   = blockIdx.x;              // batch index == 1024-token block
    const int grp  = blockIdx.y;
    const int st0  = (grp * NST) / NGROUPS;
    const int st1  = ((grp + 1) * NST) / NGROUPS;

    // A fragments for 8 m16 tiles (fp16, rows = tokens, k = dims)
    const float* xp = x + (size_t)bx * (DIM * 1024);
    const int trow = wid * 128 + gid;
    const int k0 = 2 * tg;
    uint32_t A[8][4];
#pragma unroll
    for (int m = 0; m < 8; m++) {
        int t0 = trow + m * 16, t1 = t0 + 8;
        __half2 p0 = __halves2half2(__float2half_rn(xp[k0 * 1024 + t0]),
                                    __float2half_rn(xp[(k0 + 1) * 1024 + t0]));
        __half2 p1 = __halves2half2(__float2half_rn(xp[k0 * 1024 + t1]),
                                    __float2half_rn(xp[(k0 + 1) * 1024 + t1]));
        __half2 p2 = __halves2half2(__float2half_rn(xp[(k0 + 8) * 1024 + t0]),
                                    __float2half_rn(xp[(k0 + 9) * 1024 + t0]));
        __half2 p3 = __halves2half2(__float2half_rn(xp[(k0 + 8) * 1024 + t1]),
                                    __float2half_rn(xp[(k0 + 9) * 1024 + t1]));
        A[m][0] = *(uint32_t*)&p0; A[m][1] = *(uint32_t*)&p1;
        A[m][2] = *(uint32_t*)&p2; A[m][3] = *(uint32_t*)&p3;
    }

    // prefetch first supertile
    {
        int st = st0;
        if (tid < 208) {
            if (tid < 192) {
                int row = tid / 3, ch = tid % 3;
                cpasync16(&sB[0][row * BW + ch * 4],
                          g_B + (size_t)(st * STC + row) * BW + ch * 4);
            } else {
                int v = tid - 192;
                cpasync16(&sBias[0][v * 4], g_bias + st * STC + v * 4);
            }
        }
        CP_COMMIT();
    }

    for (int st = st0; st < st1; st++) {
        const int buf = (st - st0) & 1;
        if (st + 1 < st1) {
            if (tid < 208) {
                if (tid < 192) {
                    int row = tid / 3, ch = tid % 3;
                    cpasync16(&sB[buf ^ 1][row * BW + ch * 4],
                              g_B + (size_t)((st + 1) * STC + row) * BW + ch * 4);
                } else {
                    int v = tid - 192;
                    cpasync16(&sBias[buf ^ 1][v * 4], g_bias + (st + 1) * STC + v * 4);
                }
            }
            CP_COMMIT();
            CP_WAIT(1);
        } else {
            CP_WAIT(0);
        }
        __syncthreads();

        float rmax0[8], rmax1[8];
#pragma unroll
        for (int m = 0; m < 8; m++) { rmax0[m] = NINF; rmax1[m] = NINF; }

#pragma unroll
        for (int j = 0; j < 8; j++) {         // 8-code tiles within supertile
            uint32_t b0 = sB[buf][(j * 8 + gid) * BW + tg];
            uint32_t b1 = sB[buf][(j * 8 + gid) * BW + tg + 4];
            float2 bb = *(float2*)&sBias[buf][j * 8 + 2 * tg];
            float z = 0.0f;
#pragma unroll
            for (int m = 0; m < 8; m++) {
                float c0, c1, c2, c3;
                asm volatile(
                    "mma.sync.aligned.m16n8k16.row.col.f32.f16.f16.f32 "
                    "{%0,%1,%2,%3}, {%4,%5,%6,%7}, {%8,%9}, {%10,%10,%10,%10};"
                    : "=f"(c0), "=f"(c1), "=f"(c2), "=f"(c3)
                    : "r"(A[m][0]), "r"(A[m][1]), "r"(A[m][2]), "r"(A[m][3]),
                      "r"(b0), "r"(b1), "f"(z));
                c0 += bb.x; c1 += bb.y; c2 += bb.x; c3 += bb.y;
                rmax0[m] = fmaxf(rmax0[m], fmaxf(c0, c1));
                rmax1[m] = fmaxf(rmax1[m], fmaxf(c2, c3));
            }
        }

        // cross-lane (4 lanes share a row) max, then store tile maxima
#pragma unroll
        for (int m = 0; m < 8; m++) {
            float v0 = rmax0[m], v1 = rmax1[m];
            v0 = fmaxf(v0, __shfl_xor_sync(0xffffffffu, v0, 1));
            v0 = fmaxf(v0, __shfl_xor_sync(0xffffffffu, v0, 2));
            v1 = fmaxf(v1, __shfl_xor_sync(0xffffffffu, v1, 1));
            v1 = fmaxf(v1, __shfl_xor_sync(0xffffffffu, v1, 2));
            if (tg == 0) {
                int tok = bx * 1024 + trow + m * 16;
                g_tb[(size_t)st * TOKENS + tok]     = v0;
                g_tb[(size_t)st * TOKENS + tok + 8] = v1;
            }
        }
        __syncthreads();   // compute done before next cp.async overwrites buf
    }
}

// ---------------------------------------------------------------------------
// Phase 2: exact fp32 rescore of candidate supertiles + gather + error.
// ---------------------------------------------------------------------------
__global__ __launch_bounds__(256) void finish_kernel(const float* __restrict__ x,
                                                     const float* __restrict__ cb,
                                                     float* __restrict__ out) {
    int token = blockIdx.x * 256 + threadIdx.x;
    int bb = token >> 10, t = token & 1023;

    float xr[DIM];
#pragma unroll
    for (int d = 0; d < DIM; d++) xr[d] = x[(size_t)bb * (DIM * 1024) + d * 1024 + t];

    float m = NINF;
#pragma unroll 8
    for (int ti = 0; ti < NST; ti++)
        m = fmaxf(m, g_tb[(size_t)ti * TOKENS + token]);
    const float thr = m - MARGIN;

    float best = NINF;
    int   bi   = 0;
    for (int ti = 0; ti < NST; ti++) {
        if (g_tb[(size_t)ti * TOKENS + token] < thr) continue;
        const int c0 = ti * STC;
        for (int c = c0; c < c0 + STC; c++) {
            const float* cr = cb + (size_t)c * DIM;
            float acc = 0.0f, h = 0.0f;
#pragma unroll
            for (int d = 0; d < DIM; d++) {
                float v = cr[d];
                acc = fmaf(v, xr[d], acc);
                h   = fmaf(v, v, h);
            }
            float s = acc - 0.5f * h;
            if (s > best) { best = s; bi = c; }   // strict >: first index wins
        }
    }

    const float* q = cb + (size_t)bi * DIM;
    float err = 0.0f;
#pragma unroll
    for (int d = 0; d < DIM; d++) {
        float qd = q[d];
        float df = qd - xr[d];
        err = fmaf(df, df, err);
        out[(size_t)bb * (DIM * 1024) + d * 1024 + t] = qd;
    }
    g_err[token] = err;
}

// ---------------------------------------------------------------------------
// Phase 3: deterministic loss reduction.
// ---------------------------------------------------------------------------
__global__ __launch_bounds__(1024) void loss_kernel(float* __restrict__ out,
                                                    int out_size) {
    __shared__ float s[1024];
    int tid = threadIdx.x;
    float v = 0.0f;
#pragma unroll
    for (int i = 0; i < TOKENS / 1024; i++)
        v += g_err[tid * (TOKENS / 1024) + i];
    s[tid] = v;
    __syncthreads();
    for (int stride = 512; stride > 0; stride >>= 1) {
        if (tid < stride) s[tid] += s[tid + stride];
        __syncthreads();
    }
    if (tid == 0 && out_size > NCODES)
        out[NCODES] = s[0] / (float)(TOKENS * DIM);
}

// ---------------------------------------------------------------------------
extern "C" void kernel_launch(void* const* d_in, const int* in_sizes, int n_in,
                              void* d_out, int out_size) {
    const float* x  = (const float*)d_in[0];   // [4,16,1024]
    const float* cb = (const float*)d_in[1];   // [65536,16]
    float* out = (float*)d_out;

    prep_kernel<<<NCODES / 256, 256>>>(cb);

    dim3 grid(MCTAS, NGROUPS);
    scan_kernel<<<grid, 256>>>(x);

    finish_kernel<<<TOKENS / 256, 256>>>(x, cb, out);

    loss_kernel<<<1, 1024>>>(out, out_size);
}